// round 4
// baseline (speedup 1.0000x reference)
#include <cuda_runtime.h>
#include <mma.h>
#include <math.h>

using namespace nvcuda;

#define NN   100000
#define EE   500000
#define ETOT (EE + NN)
#define GG   1000

// ---------------- device scratch (static; no runtime allocation) ----------------
__device__ float d_bufA[(size_t)NN * 256];
__device__ float d_bufB[(size_t)NN * 256];
__device__ float d_as[NN];
__device__ float d_ad[NN];
__device__ int   d_rowptr[NN + 1];
__device__ int   d_cur[NN];
__device__ int   d_col[ETOT];
__device__ float d_gsum[GG * 32];
__device__ float d_gcnt[GG];
__device__ int   d_blocksum[160];
__device__ int   d_total;

// ---------------- MLP: x[N,1] -> 16 -> 32 -> 64 (relu each), warp per node ------
__global__ void mlp_kernel(const float* __restrict__ x,
                           const float* __restrict__ w1, const float* __restrict__ b1,
                           const float* __restrict__ w2, const float* __restrict__ b2,
                           const float* __restrict__ w3, const float* __restrict__ b3,
                           float* __restrict__ out, int n) {
    __shared__ float s_w1[16], s_b1[16];
    __shared__ float s_w2t[16 * 32];
    __shared__ float s_b2[32];
    __shared__ float s_w3t[32 * 64];
    __shared__ float s_b3[64];

    int tid = threadIdx.x;
    if (tid < 16) { s_w1[tid] = w1[tid]; s_b1[tid] = b1[tid]; }
    if (tid < 32) s_b2[tid] = b2[tid];
    if (tid < 64) s_b3[tid] = b3[tid];
    for (int idx = tid; idx < 32 * 16; idx += blockDim.x) {
        int o = idx / 16, k = idx % 16;
        s_w2t[k * 32 + o] = w2[idx];
    }
    for (int idx = tid; idx < 64 * 32; idx += blockDim.x) {
        int o = idx / 32, k = idx % 32;
        s_w3t[k * 64 + o] = w3[idx];
    }
    __syncthreads();

    int warp = (blockIdx.x * blockDim.x + tid) >> 5;
    int lane = tid & 31;
    if (warp >= n) return;

    float xv = x[warp];
    float h1[16];
#pragma unroll
    for (int j = 0; j < 16; j++) {
        float v = s_w1[j] * xv + s_b1[j];
        h1[j] = v > 0.f ? v : 0.f;
    }
    float h2;
    {
        float acc = s_b2[lane];
#pragma unroll
        for (int k = 0; k < 16; k++) acc += s_w2t[k * 32 + lane] * h1[k];
        h2 = acc > 0.f ? acc : 0.f;
    }
#pragma unroll
    for (int j2 = 0; j2 < 2; j2++) {
        int j = lane + 32 * j2;
        float acc = s_b3[j];
#pragma unroll
        for (int k = 0; k < 32; k++)
            acc += __shfl_sync(0xffffffffu, h2, k) * s_w3t[k * 64 + j];
        out[(size_t)warp * 64 + j] = acc > 0.f ? acc : 0.f;
    }
}

// ---------------- CSR build (dst -> list of src), self-loops included -----------
__global__ void init_deg_kernel(int n) {
    int i = blockIdx.x * blockDim.x + threadIdx.x;
    if (i < n) d_cur[i] = 1;
}
__global__ void count_deg_kernel(const int* __restrict__ dst, int E) {
    int e = blockIdx.x * blockDim.x + threadIdx.x;
    if (e < E) atomicAdd(&d_cur[dst[e]], 1);
}
__global__ void scan_block_kernel(int n) {
    __shared__ int warpsum[32];
    int i = blockIdx.x * 1024 + threadIdx.x;
    int lane = threadIdx.x & 31, wid = threadIdx.x >> 5;
    int v = (i < n) ? d_cur[i] : 0;
    int x = v;
#pragma unroll
    for (int o = 1; o < 32; o <<= 1) {
        int t = __shfl_up_sync(0xffffffffu, x, o);
        if (lane >= o) x += t;
    }
    if (lane == 31) warpsum[wid] = x;
    __syncthreads();
    if (wid == 0) {
        int s = warpsum[lane];
#pragma unroll
        for (int o = 1; o < 32; o <<= 1) {
            int t = __shfl_up_sync(0xffffffffu, s, o);
            if (lane >= o) s += t;
        }
        warpsum[lane] = s;
    }
    __syncthreads();
    int base = wid ? warpsum[wid - 1] : 0;
    int incl = base + x;
    if (i < n) d_rowptr[i] = incl - v;
    if (threadIdx.x == 1023) d_blocksum[blockIdx.x] = incl;
}
__global__ void scan_sums_kernel(int nb) {
    __shared__ int ws[4];
    int lane = threadIdx.x & 31, wid = threadIdx.x >> 5;
    int v = ((int)threadIdx.x < nb) ? d_blocksum[threadIdx.x] : 0;
    int x = v;
#pragma unroll
    for (int o = 1; o < 32; o <<= 1) {
        int t = __shfl_up_sync(0xffffffffu, x, o);
        if (lane >= o) x += t;
    }
    if (lane == 31) ws[wid] = x;
    __syncthreads();
    int add = 0;
    for (int w0 = 0; w0 < wid; w0++) add += ws[w0];
    int incl = add + x;
    d_blocksum[threadIdx.x] = incl - v;
    if ((int)threadIdx.x == nb - 1) d_total = incl;
}
__global__ void scan_add_kernel(int n) {
    int i = blockIdx.x * 1024 + threadIdx.x;
    if (i < n) d_rowptr[i] += d_blocksum[blockIdx.x];
    else if (i == n) d_rowptr[n] = d_total;
}
__global__ void fill_self_kernel(int n) {
    int i = blockIdx.x * blockDim.x + threadIdx.x;
    if (i < n) {
        int r = d_rowptr[i];
        d_col[r] = i;
        d_cur[i] = r + 1;
    }
}
__global__ void scatter_edges_kernel(const int* __restrict__ src,
                                     const int* __restrict__ dst, int E) {
    int e = blockIdx.x * blockDim.x + threadIdx.x;
    if (e < E) {
        int p = atomicAdd(&d_cur[dst[e]], 1);
        d_col[p] = src[e];
    }
}

// ---------------- zero alpha accumulators ---------------------------------------
__global__ void zero_alpha_kernel(int n) {
    int i = blockIdx.x * blockDim.x + threadIdx.x;
    if (i < n) { d_as[i] = 0.f; d_ad[i] = 0.f; }
}

// ---------------- TF32 tensor-core GEMM with fused alpha epilogue ----------------
// C[n,O] = A[n,I] @ W[O,I]^T ; also d_as[r] += C_row . a_s (partial over this
// block's 64 columns), d_ad likewise. 128x64 block tile, BK=64, 256 threads.
#define GLD 68   // padded smem row stride (floats) for BK=64
__global__ void gemm_tf32_kernel(const float* __restrict__ A, const float* __restrict__ W,
                                 float* __restrict__ C,
                                 const float* __restrict__ a_s,
                                 const float* __restrict__ a_d,
                                 int n, int I, int O) {
    __shared__ float As[128 * GLD];
    __shared__ float Bs[64 * GLD];
    __shared__ float s_as[64], s_ad[64];
    int tid = threadIdx.x;
    int w = tid >> 5;
    int wm = w & 3, wn = w >> 2;
    int bm = blockIdx.y * 128, bn = blockIdx.x * 64;

    if (tid < 64) {
        int c = bn + tid;
        s_as[tid] = (c < O) ? a_s[c] : 0.f;
        s_ad[tid] = (c < O) ? a_d[c] : 0.f;
    }

    wmma::fragment<wmma::accumulator, 16, 16, 8, float> acc[2][2];
#pragma unroll
    for (int i = 0; i < 2; i++)
#pragma unroll
        for (int j = 0; j < 2; j++) wmma::fill_fragment(acc[i][j], 0.f);

    for (int k0 = 0; k0 < I; k0 += 64) {
        // A tile: 128 rows x 64 floats = 2048 float4 -> 8 per thread
#pragma unroll
        for (int t = 0; t < 8; t++) {
            int idx = tid * 8 + t;            // 0..2047
            int r = idx >> 4, kq = (idx & 15) * 4;
            int ar = bm + r;
            float4 av = make_float4(0.f, 0.f, 0.f, 0.f);
            if (ar < n) av = *(const float4*)(A + (size_t)ar * I + k0 + kq);
            *(float4*)(As + r * GLD + kq) = av;
        }
        // B tile: 64 rows x 64 floats = 1024 float4 -> 4 per thread
#pragma unroll
        for (int t = 0; t < 4; t++) {
            int idx = tid * 4 + t;            // 0..1023
            int r = idx >> 4, kq = (idx & 15) * 4;
            int br = bn + r;
            float4 bv = make_float4(0.f, 0.f, 0.f, 0.f);
            if (br < O) bv = *(const float4*)(W + (size_t)br * I + k0 + kq);
            *(float4*)(Bs + r * GLD + kq) = bv;
        }
        __syncthreads();
#pragma unroll
        for (int kk = 0; kk < 64; kk += 8) {
            wmma::fragment<wmma::matrix_a, 16, 16, 8, wmma::precision::tf32, wmma::row_major> af[2];
            wmma::fragment<wmma::matrix_b, 16, 16, 8, wmma::precision::tf32, wmma::col_major> bf[2];
            wmma::load_matrix_sync(af[0], As + (wm * 32) * GLD + kk, GLD);
            wmma::load_matrix_sync(af[1], As + (wm * 32 + 16) * GLD + kk, GLD);
            wmma::load_matrix_sync(bf[0], Bs + (wn * 32) * GLD + kk, GLD);
            wmma::load_matrix_sync(bf[1], Bs + (wn * 32 + 16) * GLD + kk, GLD);
#pragma unroll
            for (int i = 0; i < 2; i++)
#pragma unroll
                for (int j = 0; j < 2; j++)
                    wmma::mma_sync(acc[i][j], af[i], bf[j], acc[i][j]);
        }
        __syncthreads();
    }

    // epilogue: stage output tile in smem (reuse As, stride GLD), then
    // coalesced copy to C + per-row alpha partial dots.
#pragma unroll
    for (int i = 0; i < 2; i++)
#pragma unroll
        for (int j = 0; j < 2; j++)
            wmma::store_matrix_sync(As + (wm * 32 + i * 16) * GLD + wn * 32 + j * 16,
                                    acc[i][j], GLD, wmma::mem_row_major);
    __syncthreads();

    {
        int r = tid >> 1;                 // 0..127
        int half = (tid & 1) * 32;        // 0 or 32
        int gr = bm + r;
        int gc = bn + half;
        if (gr < n && gc < O) {
            float sa = 0.f, sd = 0.f;
            const float* srow = As + r * GLD + half;
            float* crow = C + (size_t)gr * O + gc;
#pragma unroll
            for (int q = 0; q < 8; q++) {
                float4 v = *(const float4*)(srow + q * 4);
                *(float4*)(crow + q * 4) = v;
                int c = half + q * 4;
                sa += v.x * s_as[c] + v.y * s_as[c + 1] + v.z * s_as[c + 2] + v.w * s_as[c + 3];
                sd += v.x * s_ad[c] + v.y * s_ad[c + 1] + v.z * s_ad[c + 2] + v.w * s_ad[c + 3];
            }
            atomicAdd(&d_as[gr], sa);
            atomicAdd(&d_ad[gr], sd);
        }
    }
}

// ---------------- GAT aggregate: warp per dst node, CSR gather, vectorized -------
// ZPOOL: zero pool buffers (run on the layer BEFORE the pooled layer)
// POOL:  fuse mean-pool accumulation (last layer, CPL==1)
template <int CPL, bool ZPOOL, bool POOL>
__global__ void gat_agg_kernel(const float* __restrict__ hlin,
                               const float* __restrict__ bias,
                               float* __restrict__ out,
                               const int* __restrict__ batch, int n, int O) {
    int gt = blockIdx.x * blockDim.x + threadIdx.x;
    if (ZPOOL) {
        if (gt < GG * 32) d_gsum[gt] = 0.f;
        if (gt < GG) d_gcnt[gt] = 0.f;
    }
    int warp = gt >> 5;
    int lane = threadIdx.x & 31;
    if (warp >= n) return;
    int s = d_rowptr[warp];
    int e = d_rowptr[warp + 1];
    float adi = d_ad[warp];

    float m = -1e30f;
    for (int p = s + lane; p < e; p += 32) {
        float v = d_as[d_col[p]] + adi;
        v = v > 0.f ? v : 0.2f * v;
        m = fmaxf(m, v);
    }
#pragma unroll
    for (int o = 16; o; o >>= 1) m = fmaxf(m, __shfl_xor_sync(0xffffffffu, m, o));

    float den = 0.f;
    float acc[CPL];
#pragma unroll
    for (int c = 0; c < CPL; c++) acc[c] = 0.f;

    for (int p0 = s; p0 < e; p0 += 32) {
        int p = p0 + lane;
        float w = 0.f;
        int src = 0;
        if (p < e) {
            src = d_col[p];
            float v = d_as[src] + adi;
            v = v > 0.f ? v : 0.2f * v;
            w = __expf(v - m);
            den += w;
        }
        int cnt = min(32, e - p0);
        for (int q = 0; q < cnt; q++) {
            float wq = __shfl_sync(0xffffffffu, w, q);
            int   sq = __shfl_sync(0xffffffffu, src, q);
            const float* row = hlin + (size_t)sq * O;
            if (CPL == 1) {
                acc[0] += wq * row[lane];
            } else if (CPL == 2) {
                float2 v2 = ((const float2*)row)[lane];
                acc[0] += wq * v2.x; acc[1] += wq * v2.y;
            } else if (CPL == 4) {
                float4 v4 = ((const float4*)row)[lane];
                acc[0] += wq * v4.x; acc[1] += wq * v4.y;
                acc[2] += wq * v4.z; acc[3] += wq * v4.w;
            } else {
                float4 v4 = ((const float4*)row)[lane];
                float4 u4 = ((const float4*)row)[lane + 32];
                acc[0] += wq * v4.x; acc[1] += wq * v4.y;
                acc[2] += wq * v4.z; acc[3] += wq * v4.w;
                acc[4] += wq * u4.x; acc[5] += wq * u4.y;
                acc[6] += wq * u4.z; acc[7] += wq * u4.w;
            }
        }
    }
#pragma unroll
    for (int o = 16; o; o >>= 1) den += __shfl_xor_sync(0xffffffffu, den, o);
    float inv = 1.f / den;

    float* orow = out + (size_t)warp * O;
    if (CPL == 1) {
        float v = acc[0] * inv + bias[lane];
        v = v > 0.f ? v : 0.f;
        orow[lane] = v;
        if (POOL) {
            int b = batch[warp];
            atomicAdd(&d_gsum[b * 32 + lane], v);
            if (lane == 0) atomicAdd(&d_gcnt[b], 1.f);
        }
    } else if (CPL == 2) {
        float2 b2 = ((const float2*)bias)[lane];
        float2 r2;
        r2.x = acc[0] * inv + b2.x; r2.x = r2.x > 0.f ? r2.x : 0.f;
        r2.y = acc[1] * inv + b2.y; r2.y = r2.y > 0.f ? r2.y : 0.f;
        ((float2*)orow)[lane] = r2;
    } else if (CPL == 4) {
        float4 b4 = ((const float4*)bias)[lane];
        float4 r4;
        r4.x = acc[0] * inv + b4.x; r4.x = r4.x > 0.f ? r4.x : 0.f;
        r4.y = acc[1] * inv + b4.y; r4.y = r4.y > 0.f ? r4.y : 0.f;
        r4.z = acc[2] * inv + b4.z; r4.z = r4.z > 0.f ? r4.z : 0.f;
        r4.w = acc[3] * inv + b4.w; r4.w = r4.w > 0.f ? r4.w : 0.f;
        ((float4*)orow)[lane] = r4;
    } else {
        float4 b4 = ((const float4*)bias)[lane];
        float4 c4 = ((const float4*)bias)[lane + 32];
        float4 r4, s4;
        r4.x = acc[0] * inv + b4.x; r4.x = r4.x > 0.f ? r4.x : 0.f;
        r4.y = acc[1] * inv + b4.y; r4.y = r4.y > 0.f ? r4.y : 0.f;
        r4.z = acc[2] * inv + b4.z; r4.z = r4.z > 0.f ? r4.z : 0.f;
        r4.w = acc[3] * inv + b4.w; r4.w = r4.w > 0.f ? r4.w : 0.f;
        s4.x = acc[4] * inv + c4.x; s4.x = s4.x > 0.f ? s4.x : 0.f;
        s4.y = acc[5] * inv + c4.y; s4.y = s4.y > 0.f ? s4.y : 0.f;
        s4.z = acc[6] * inv + c4.z; s4.z = s4.z > 0.f ? s4.z : 0.f;
        s4.w = acc[7] * inv + c4.w; s4.w = s4.w > 0.f ? s4.w : 0.f;
        ((float4*)orow)[lane] = r4;
        ((float4*)orow)[lane + 32] = s4;
    }
}

// ---------------- final linear + sigmoid ------------------------------------------
__global__ void final_kernel(const float* __restrict__ lw, const float* __restrict__ lb,
                             float* __restrict__ out) {
    int g = blockIdx.x * blockDim.x + threadIdx.x;
    if (g >= GG) return;
    float cnt = fmaxf(d_gcnt[g], 1.f);
    float acc = lb[0];
#pragma unroll
    for (int c = 0; c < 32; c++) acc += (d_gsum[g * 32 + c] / cnt) * lw[c];
    out[g] = 1.f / (1.f + __expf(-acc));
}

// ---------------- launch ----------------------------------------------------------
extern "C" void kernel_launch(void* const* d_in, const int* in_sizes, int n_in,
                              void* d_out, int out_size) {
    const float* x     = (const float*)d_in[0];
    const int*   ei    = (const int*)d_in[1];
    const int*   batch = (const int*)d_in[2];
    const float* w1 = (const float*)d_in[3]; const float* b1 = (const float*)d_in[4];
    const float* w2 = (const float*)d_in[5]; const float* b2 = (const float*)d_in[6];
    const float* w3 = (const float*)d_in[7]; const float* b3 = (const float*)d_in[8];
    float* out = (float*)d_out;

    int n = in_sizes[0];
    int E = in_sizes[1] / 2;
    const int* src = ei;
    const int* dst = ei + E;

    float* bufA; float* bufB;
    cudaGetSymbolAddress((void**)&bufA, d_bufA);
    cudaGetSymbolAddress((void**)&bufB, d_bufB);

    const int TPB = 256;
    int warpBlocks = (n * 32 + TPB - 1) / TPB;

    mlp_kernel<<<warpBlocks, TPB>>>(x, w1, b1, w2, b2, w3, b3, bufA, n);

    init_deg_kernel<<<(n + TPB - 1) / TPB, TPB>>>(n);
    count_deg_kernel<<<(E + TPB - 1) / TPB, TPB>>>(dst, E);
    int nb = (n + 1023) / 1024;
    scan_block_kernel<<<nb, 1024>>>(n);
    scan_sums_kernel<<<1, 128>>>(nb);
    scan_add_kernel<<<(n + 1024) / 1024, 1024>>>(n);
    fill_self_kernel<<<(n + TPB - 1) / TPB, TPB>>>(n);
    scatter_edges_kernel<<<(E + TPB - 1) / TPB, TPB>>>(src, dst, E);

    struct Layer { const float *W, *as_, *ad_, *b; int I, O; };
    Layer L[5] = {
        { (const float*)d_in[9],  (const float*)d_in[10], (const float*)d_in[11], (const float*)d_in[12],  64, 128 },
        { (const float*)d_in[13], (const float*)d_in[14], (const float*)d_in[15], (const float*)d_in[16], 128, 256 },
        { (const float*)d_in[17], (const float*)d_in[18], (const float*)d_in[19], (const float*)d_in[20], 256, 128 },
        { (const float*)d_in[21], (const float*)d_in[22], (const float*)d_in[23], (const float*)d_in[24], 128,  64 },
        { (const float*)d_in[25], (const float*)d_in[26], (const float*)d_in[27], (const float*)d_in[28],  64,  32 },
    };

    for (int l = 0; l < 5; l++) {
        int I = L[l].I, O = L[l].O;
        zero_alpha_kernel<<<(n + TPB - 1) / TPB, TPB>>>(n);
        dim3 grid((O + 63) / 64, (n + 127) / 128);
        gemm_tf32_kernel<<<grid, 256>>>(bufA, L[l].W, bufB, L[l].as_, L[l].ad_, n, I, O);
        switch (O >> 5) {
            case 1: gat_agg_kernel<1, false, true ><<<warpBlocks, TPB>>>(bufB, L[l].b, bufA, batch, n, O); break;
            case 2: gat_agg_kernel<2, true,  false><<<warpBlocks, TPB>>>(bufB, L[l].b, bufA, batch, n, O); break;
            case 4: gat_agg_kernel<4, false, false><<<warpBlocks, TPB>>>(bufB, L[l].b, bufA, batch, n, O); break;
            case 8: gat_agg_kernel<8, false, false><<<warpBlocks, TPB>>>(bufB, L[l].b, bufA, batch, n, O); break;
        }
    }

    final_kernel<<<(GG + TPB - 1) / TPB, TPB>>>((const float*)d_in[29],
                                                (const float*)d_in[30], out);
}

// round 5
// speedup vs baseline: 1.1046x; 1.1046x over previous
#include <cuda_runtime.h>
#include <cuda_bf16.h>
#include <mma.h>
#include <math.h>

using namespace nvcuda;

#define NN   100000
#define EE   500000
#define ETOT (EE + NN)
#define GG   1000

// ---------------- device scratch (static; no runtime allocation) ----------------
__device__ float          d_bufA[(size_t)NN * 256];     // fp32 node features (agg out / gemm in)
__device__ __nv_bfloat16  d_bufBh[(size_t)NN * 256];    // bf16 gemm output (gathered by agg)
__device__ float d_as0[NN], d_ad0[NN];                  // alpha ping
__device__ float d_as1[NN], d_ad1[NN];                  // alpha pong
__device__ float d_was[256], d_wad[256];                // W^T a_s / W^T a_d for next layer
__device__ int   d_rowptr[NN + 1];
__device__ int   d_cur[NN];
__device__ int   d_col[ETOT];
__device__ float d_gsum[GG * 32];
__device__ float d_gcnt[GG];
__device__ int   d_blocksum[160];
__device__ int   d_total;

// ---------------- prep: w_as = W^T a_s, w_ad = W^T a_d (tiny) --------------------
__global__ void prep_w_kernel(const float* __restrict__ W, const float* __restrict__ as_,
                              const float* __restrict__ ad_, int I, int O) {
    int k = threadIdx.x;
    if (k >= I) return;
    float sa = 0.f, sd = 0.f;
    for (int o = 0; o < O; o++) {
        float w = W[(size_t)o * I + k];
        sa += w * as_[o];
        sd += w * ad_[o];
    }
    d_was[k] = sa;
    d_wad[k] = sd;
}

// ---------------- MLP: x[N,1]->16->32->64 relu; fused layer-1 alpha --------------
__global__ void mlp_kernel(const float* __restrict__ x,
                           const float* __restrict__ w1, const float* __restrict__ b1,
                           const float* __restrict__ w2, const float* __restrict__ b2,
                           const float* __restrict__ w3, const float* __restrict__ b3,
                           float* __restrict__ out,
                           float* __restrict__ as_out, float* __restrict__ ad_out, int n) {
    __shared__ float s_w1[16], s_b1[16];
    __shared__ float s_w2t[16 * 32];
    __shared__ float s_b2[32];
    __shared__ float s_w3t[32 * 64];
    __shared__ float s_b3[64];
    __shared__ float s_was[64], s_wad[64];

    int tid = threadIdx.x;
    if (tid < 16) { s_w1[tid] = w1[tid]; s_b1[tid] = b1[tid]; }
    if (tid < 32) s_b2[tid] = b2[tid];
    if (tid < 64) { s_b3[tid] = b3[tid]; s_was[tid] = d_was[tid]; s_wad[tid] = d_wad[tid]; }
    for (int idx = tid; idx < 32 * 16; idx += blockDim.x) {
        int o = idx / 16, k = idx % 16;
        s_w2t[k * 32 + o] = w2[idx];
    }
    for (int idx = tid; idx < 64 * 32; idx += blockDim.x) {
        int o = idx / 32, k = idx % 32;
        s_w3t[k * 64 + o] = w3[idx];
    }
    __syncthreads();

    int warp = (blockIdx.x * blockDim.x + tid) >> 5;
    int lane = tid & 31;
    if (warp >= n) return;

    float xv = x[warp];
    float h1[16];
#pragma unroll
    for (int j = 0; j < 16; j++) {
        float v = s_w1[j] * xv + s_b1[j];
        h1[j] = v > 0.f ? v : 0.f;
    }
    float h2;
    {
        float acc = s_b2[lane];
#pragma unroll
        for (int k = 0; k < 16; k++) acc += s_w2t[k * 32 + lane] * h1[k];
        h2 = acc > 0.f ? acc : 0.f;
    }
    float v0, v1;
#pragma unroll
    for (int j2 = 0; j2 < 2; j2++) {
        int j = lane + 32 * j2;
        float acc = s_b3[j];
#pragma unroll
        for (int k = 0; k < 32; k++)
            acc += __shfl_sync(0xffffffffu, h2, k) * s_w3t[k * 64 + j];
        acc = acc > 0.f ? acc : 0.f;
        out[(size_t)warp * 64 + j] = acc;
        if (j2 == 0) v0 = acc; else v1 = acc;
    }
    // fused alpha for GAT layer 1
    float sa = v0 * s_was[lane] + v1 * s_was[lane + 32];
    float sd = v0 * s_wad[lane] + v1 * s_wad[lane + 32];
#pragma unroll
    for (int o = 16; o; o >>= 1) {
        sa += __shfl_xor_sync(0xffffffffu, sa, o);
        sd += __shfl_xor_sync(0xffffffffu, sd, o);
    }
    if (lane == 0) { as_out[warp] = sa; ad_out[warp] = sd; }
}

// ---------------- CSR build ------------------------------------------------------
__global__ void init_deg_kernel(int n) {
    int i = blockIdx.x * blockDim.x + threadIdx.x;
    if (i < n) d_cur[i] = 1;
}
__global__ void count_deg_kernel(const int* __restrict__ dst, int E) {
    int e = blockIdx.x * blockDim.x + threadIdx.x;
    if (e < E) atomicAdd(&d_cur[dst[e]], 1);
}
__global__ void scan_block_kernel(int n) {
    __shared__ int warpsum[32];
    int i = blockIdx.x * 1024 + threadIdx.x;
    int lane = threadIdx.x & 31, wid = threadIdx.x >> 5;
    int v = (i < n) ? d_cur[i] : 0;
    int x = v;
#pragma unroll
    for (int o = 1; o < 32; o <<= 1) {
        int t = __shfl_up_sync(0xffffffffu, x, o);
        if (lane >= o) x += t;
    }
    if (lane == 31) warpsum[wid] = x;
    __syncthreads();
    if (wid == 0) {
        int s = warpsum[lane];
#pragma unroll
        for (int o = 1; o < 32; o <<= 1) {
            int t = __shfl_up_sync(0xffffffffu, s, o);
            if (lane >= o) s += t;
        }
        warpsum[lane] = s;
    }
    __syncthreads();
    int base = wid ? warpsum[wid - 1] : 0;
    int incl = base + x;
    if (i < n) d_rowptr[i] = incl - v;
    if (threadIdx.x == 1023) d_blocksum[blockIdx.x] = incl;
}
__global__ void scan_sums_kernel(int nb) {
    __shared__ int ws[4];
    int lane = threadIdx.x & 31, wid = threadIdx.x >> 5;
    int v = ((int)threadIdx.x < nb) ? d_blocksum[threadIdx.x] : 0;
    int x = v;
#pragma unroll
    for (int o = 1; o < 32; o <<= 1) {
        int t = __shfl_up_sync(0xffffffffu, x, o);
        if (lane >= o) x += t;
    }
    if (lane == 31) ws[wid] = x;
    __syncthreads();
    int add = 0;
    for (int w0 = 0; w0 < wid; w0++) add += ws[w0];
    int incl = add + x;
    d_blocksum[threadIdx.x] = incl - v;
    if ((int)threadIdx.x == nb - 1) d_total = incl;
}
__global__ void scan_add_kernel(int n) {
    int i = blockIdx.x * 1024 + threadIdx.x;
    if (i < n) d_rowptr[i] += d_blocksum[blockIdx.x];
    else if (i == n) d_rowptr[n] = d_total;
}
__global__ void fill_self_kernel(int n) {
    int i = blockIdx.x * blockDim.x + threadIdx.x;
    if (i < n) {
        int r = d_rowptr[i];
        d_col[r] = i;
        d_cur[i] = r + 1;
    }
}
__global__ void scatter_edges_kernel(const int* __restrict__ src,
                                     const int* __restrict__ dst, int E) {
    int e = blockIdx.x * blockDim.x + threadIdx.x;
    if (e < E) {
        int p = atomicAdd(&d_cur[dst[e]], 1);
        d_col[p] = src[e];
    }
}

// ---------------- TF32 GEMM: C_bf16[n,O] = A[n,I] @ W[O,I]^T ---------------------
// 128x64 tile, BK=32, 256 threads, bf16 output via smem half-tile staging.
#define GLD 36
__global__ void gemm_tf32_kernel(const float* __restrict__ A, const float* __restrict__ W,
                                 __nv_bfloat16* __restrict__ C, int n, int I, int O) {
    __shared__ float As[128 * GLD];
    __shared__ float Bs[64 * GLD];
    __shared__ float Os[64 * 65];
    int tid = threadIdx.x;
    int w = tid >> 5;
    int wm = w & 3, wn = w >> 2;
    int bm = blockIdx.y * 128, bn = blockIdx.x * 64;

    wmma::fragment<wmma::accumulator, 16, 16, 8, float> acc[2][2];
#pragma unroll
    for (int i = 0; i < 2; i++)
#pragma unroll
        for (int j = 0; j < 2; j++) wmma::fill_fragment(acc[i][j], 0.f);

    for (int k0 = 0; k0 < I; k0 += 32) {
#pragma unroll
        for (int t = 0; t < 4; t++) {
            int idx = tid * 4 + t;
            int r = idx >> 3, kq = (idx & 7) * 4;
            int ar = bm + r;
            float4 av = make_float4(0.f, 0.f, 0.f, 0.f);
            if (ar < n) av = *(const float4*)(A + (size_t)ar * I + k0 + kq);
            *(float4*)(As + r * GLD + kq) = av;
        }
#pragma unroll
        for (int t = 0; t < 2; t++) {
            int idx = tid * 2 + t;
            int r = idx >> 3, kq = (idx & 7) * 4;
            int br = bn + r;
            float4 bv = make_float4(0.f, 0.f, 0.f, 0.f);
            if (br < O) bv = *(const float4*)(W + (size_t)br * I + k0 + kq);
            *(float4*)(Bs + r * GLD + kq) = bv;
        }
        __syncthreads();
#pragma unroll
        for (int kk = 0; kk < 32; kk += 8) {
            wmma::fragment<wmma::matrix_a, 16, 16, 8, wmma::precision::tf32, wmma::row_major> af[2];
            wmma::fragment<wmma::matrix_b, 16, 16, 8, wmma::precision::tf32, wmma::col_major> bf[2];
            wmma::load_matrix_sync(af[0], As + (wm * 32) * GLD + kk, GLD);
            wmma::load_matrix_sync(af[1], As + (wm * 32 + 16) * GLD + kk, GLD);
            wmma::load_matrix_sync(bf[0], Bs + (wn * 32) * GLD + kk, GLD);
            wmma::load_matrix_sync(bf[1], Bs + (wn * 32 + 16) * GLD + kk, GLD);
#pragma unroll
            for (int i = 0; i < 2; i++)
#pragma unroll
                for (int j = 0; j < 2; j++)
                    wmma::mma_sync(acc[i][j], af[i], bf[j], acc[i][j]);
        }
        __syncthreads();
    }

    // epilogue: two 64-row halves staged in Os, converted to bf16, coalesced store
#pragma unroll
    for (int h = 0; h < 2; h++) {
        if ((wm >> 1) == h) {
            int rb = (wm & 1) * 32;
#pragma unroll
            for (int i = 0; i < 2; i++)
#pragma unroll
                for (int j = 0; j < 2; j++)
                    wmma::store_matrix_sync(Os + (rb + i * 16) * 65 + wn * 32 + j * 16,
                                            acc[i][j], 65, wmma::mem_row_major);
        }
        __syncthreads();
        {
            int r = tid >> 2;
            int cg = (tid & 3) * 16;
            int gr = bm + h * 64 + r;
            if (gr < n && bn + cg < O) {
                const float* srow = Os + r * 65 + cg;
                __nv_bfloat16* drow = C + (size_t)gr * O + bn + cg;
#pragma unroll
                for (int q = 0; q < 2; q++) {
                    __nv_bfloat162 p0 = __float22bfloat162_rn(make_float2(srow[q * 8 + 0], srow[q * 8 + 1]));
                    __nv_bfloat162 p1 = __float22bfloat162_rn(make_float2(srow[q * 8 + 2], srow[q * 8 + 3]));
                    __nv_bfloat162 p2 = __float22bfloat162_rn(make_float2(srow[q * 8 + 4], srow[q * 8 + 5]));
                    __nv_bfloat162 p3 = __float22bfloat162_rn(make_float2(srow[q * 8 + 6], srow[q * 8 + 7]));
                    uint4 u;
                    u.x = *(unsigned*)&p0; u.y = *(unsigned*)&p1;
                    u.z = *(unsigned*)&p2; u.w = *(unsigned*)&p3;
                    *(uint4*)(drow + q * 8) = u;
                }
            }
        }
        __syncthreads();
    }
}

// ---------------- GAT aggregate: warp per dst node, bf16 CSR gather --------------
// ALPHA: fused next-layer alpha from output row; ZPOOL: zero pool bufs; POOL: pool
template <int CPL, bool ZPOOL, bool POOL, bool ALPHA>
__global__ void gat_agg_kernel(const __nv_bfloat16* __restrict__ hlin,
                               const float* __restrict__ bias,
                               float* __restrict__ out,
                               const float* __restrict__ as_in,
                               const float* __restrict__ ad_in,
                               float* __restrict__ as_out,
                               float* __restrict__ ad_out,
                               const int* __restrict__ batch, int n, int O) {
    __shared__ float s_was[256], s_wad[256];
    int tid = threadIdx.x;
    if (ALPHA && tid < O) { s_was[tid] = d_was[tid]; s_wad[tid] = d_wad[tid]; }
    if (ALPHA) __syncthreads();

    int gt = blockIdx.x * blockDim.x + tid;
    if (ZPOOL) {
        if (gt < GG * 32) d_gsum[gt] = 0.f;
        if (gt < GG) d_gcnt[gt] = 0.f;
    }
    int warp = gt >> 5;
    int lane = tid & 31;
    if (warp >= n) return;
    int s = d_rowptr[warp];
    int e = d_rowptr[warp + 1];
    float adi = ad_in[warp];

    float m = -1e30f;
    for (int p = s + lane; p < e; p += 32) {
        float v = as_in[d_col[p]] + adi;
        v = v > 0.f ? v : 0.2f * v;
        m = fmaxf(m, v);
    }
#pragma unroll
    for (int o = 16; o; o >>= 1) m = fmaxf(m, __shfl_xor_sync(0xffffffffu, m, o));

    float den = 0.f;
    float acc[CPL];
#pragma unroll
    for (int c = 0; c < CPL; c++) acc[c] = 0.f;

    for (int p0 = s; p0 < e; p0 += 32) {
        int p = p0 + lane;
        float wgt = 0.f;
        int src = 0;
        if (p < e) {
            src = d_col[p];
            float v = as_in[src] + adi;
            v = v > 0.f ? v : 0.2f * v;
            wgt = __expf(v - m);
            den += wgt;
        }
        int cnt = min(32, e - p0);
        for (int q = 0; q < cnt; q++) {
            float wq = __shfl_sync(0xffffffffu, wgt, q);
            int   sq = __shfl_sync(0xffffffffu, src, q);
            const __nv_bfloat16* row = hlin + (size_t)sq * O;
            if (CPL == 1) {
                acc[0] += wq * __bfloat162float(row[lane]);
            } else if (CPL == 2) {
                float2 f0 = __bfloat1622float2(((const __nv_bfloat162*)row)[lane]);
                acc[0] += wq * f0.x; acc[1] += wq * f0.y;
            } else if (CPL == 4) {
                uint2 u = ((const uint2*)row)[lane];
                float2 f0 = __bfloat1622float2(*(__nv_bfloat162*)&u.x);
                float2 f1 = __bfloat1622float2(*(__nv_bfloat162*)&u.y);
                acc[0] += wq * f0.x; acc[1] += wq * f0.y;
                acc[2] += wq * f1.x; acc[3] += wq * f1.y;
            } else {  // CPL == 8
                uint4 u = ((const uint4*)row)[lane];
                float2 f0 = __bfloat1622float2(*(__nv_bfloat162*)&u.x);
                float2 f1 = __bfloat1622float2(*(__nv_bfloat162*)&u.y);
                float2 f2 = __bfloat1622float2(*(__nv_bfloat162*)&u.z);
                float2 f3 = __bfloat1622float2(*(__nv_bfloat162*)&u.w);
                acc[0] += wq * f0.x; acc[1] += wq * f0.y;
                acc[2] += wq * f1.x; acc[3] += wq * f1.y;
                acc[4] += wq * f2.x; acc[5] += wq * f2.y;
                acc[6] += wq * f3.x; acc[7] += wq * f3.y;
            }
        }
    }
#pragma unroll
    for (int o = 16; o; o >>= 1) den += __shfl_xor_sync(0xffffffffu, den, o);
    float inv = 1.f / den;

    // finalize: v[c] = relu(acc*inv + bias), channel = CPL*lane + c (contiguous)
    float v[CPL];
#pragma unroll
    for (int c = 0; c < CPL; c++) {
        float b = bias[CPL * lane + c];
        float t = acc[c] * inv + b;
        v[c] = t > 0.f ? t : 0.f;
    }

    float* orow = out + (size_t)warp * O;
    if (CPL == 1) {
        orow[lane] = v[0];
        if (POOL) {
            int b = batch[warp];
            atomicAdd(&d_gsum[b * 32 + lane], v[0]);
            if (lane == 0) atomicAdd(&d_gcnt[b], 1.f);
        }
    } else if (CPL == 2) {
        ((float2*)orow)[lane] = make_float2(v[0], v[1]);
    } else if (CPL == 4) {
        ((float4*)orow)[lane] = make_float4(v[0], v[1], v[2], v[3]);
    } else {
        ((float4*)orow)[2 * lane]     = make_float4(v[0], v[1], v[2], v[3]);
        ((float4*)orow)[2 * lane + 1] = make_float4(v[4], v[5], v[6], v[7]);
    }

    if (ALPHA) {
        float sa = 0.f, sd = 0.f;
#pragma unroll
        for (int c = 0; c < CPL; c++) {
            int ch = CPL * lane + c;
            sa += v[c] * s_was[ch];
            sd += v[c] * s_wad[ch];
        }
#pragma unroll
        for (int o = 16; o; o >>= 1) {
            sa += __shfl_xor_sync(0xffffffffu, sa, o);
            sd += __shfl_xor_sync(0xffffffffu, sd, o);
        }
        if (lane == 0) { as_out[warp] = sa; ad_out[warp] = sd; }
    }
}

// ---------------- final linear + sigmoid ------------------------------------------
__global__ void final_kernel(const float* __restrict__ lw, const float* __restrict__ lb,
                             float* __restrict__ out) {
    int g = blockIdx.x * blockDim.x + threadIdx.x;
    if (g >= GG) return;
    float cnt = fmaxf(d_gcnt[g], 1.f);
    float acc = lb[0];
#pragma unroll
    for (int c = 0; c < 32; c++) acc += (d_gsum[g * 32 + c] / cnt) * lw[c];
    out[g] = 1.f / (1.f + __expf(-acc));
}

// ---------------- launch ----------------------------------------------------------
extern "C" void kernel_launch(void* const* d_in, const int* in_sizes, int n_in,
                              void* d_out, int out_size) {
    const float* x     = (const float*)d_in[0];
    const int*   ei    = (const int*)d_in[1];
    const int*   batch = (const int*)d_in[2];
    const float* w1 = (const float*)d_in[3]; const float* b1 = (const float*)d_in[4];
    const float* w2 = (const float*)d_in[5]; const float* b2 = (const float*)d_in[6];
    const float* w3 = (const float*)d_in[7]; const float* b3 = (const float*)d_in[8];
    float* out = (float*)d_out;

    int n = in_sizes[0];
    int E = in_sizes[1] / 2;
    const int* src = ei;
    const int* dst = ei + E;

    float *bufA, *as0, *ad0, *as1, *ad1;
    __nv_bfloat16* bufBh;
    cudaGetSymbolAddress((void**)&bufA, d_bufA);
    cudaGetSymbolAddress((void**)&bufBh, d_bufBh);
    cudaGetSymbolAddress((void**)&as0, d_as0);
    cudaGetSymbolAddress((void**)&ad0, d_ad0);
    cudaGetSymbolAddress((void**)&as1, d_as1);
    cudaGetSymbolAddress((void**)&ad1, d_ad1);

    const int TPB = 256;
    int warpBlocks = (n * 32 + TPB - 1) / TPB;

    struct Layer { const float *W, *as_, *ad_, *b; int I, O; };
    Layer L[5] = {
        { (const float*)d_in[9],  (const float*)d_in[10], (const float*)d_in[11], (const float*)d_in[12],  64, 128 },
        { (const float*)d_in[13], (const float*)d_in[14], (const float*)d_in[15], (const float*)d_in[16], 128, 256 },
        { (const float*)d_in[17], (const float*)d_in[18], (const float*)d_in[19], (const float*)d_in[20], 256, 128 },
        { (const float*)d_in[21], (const float*)d_in[22], (const float*)d_in[23], (const float*)d_in[24], 128,  64 },
        { (const float*)d_in[25], (const float*)d_in[26], (const float*)d_in[27], (const float*)d_in[28],  64,  32 },
    };

    // prep layer-1 alpha weights, then MLP with fused alpha (-> set 0)
    prep_w_kernel<<<1, 256>>>(L[0].W, L[0].as_, L[0].ad_, L[0].I, L[0].O);
    mlp_kernel<<<warpBlocks, TPB>>>(x, w1, b1, w2, b2, w3, b3, bufA, as0, ad0, n);

    // CSR build
    init_deg_kernel<<<(n + TPB - 1) / TPB, TPB>>>(n);
    count_deg_kernel<<<(E + TPB - 1) / TPB, TPB>>>(dst, E);
    int nb = (n + 1023) / 1024;
    scan_block_kernel<<<nb, 1024>>>(n);
    scan_sums_kernel<<<1, 128>>>(nb);
    scan_add_kernel<<<(n + 1024) / 1024, 1024>>>(n);
    fill_self_kernel<<<(n + TPB - 1) / TPB, TPB>>>(n);
    scatter_edges_kernel<<<(E + TPB - 1) / TPB, TPB>>>(src, dst, E);

    for (int l = 0; l < 5; l++) {
        int I = L[l].I, O = L[l].O;
        dim3 grid((O + 63) / 64, (n + 127) / 128);
        gemm_tf32_kernel<<<grid, 256>>>(bufA, L[l].W, bufBh, n, I, O);
        if (l < 4)   // alpha weights for next layer
            prep_w_kernel<<<1, 256>>>(L[l + 1].W, L[l + 1].as_, L[l + 1].ad_,
                                      L[l + 1].I, L[l + 1].O);
        const float* asi = (l & 1) ? as1 : as0;
        const float* adi = (l & 1) ? ad1 : ad0;
        float* aso = (l & 1) ? as0 : as1;
        float* ado = (l & 1) ? ad0 : ad1;
        switch (l) {
            case 0: gat_agg_kernel<4, false, false, true ><<<warpBlocks, TPB>>>(bufBh, L[l].b, bufA, asi, adi, aso, ado, batch, n, O); break;
            case 1: gat_agg_kernel<8, false, false, true ><<<warpBlocks, TPB>>>(bufBh, L[l].b, bufA, asi, adi, aso, ado, batch, n, O); break;
            case 2: gat_agg_kernel<4, false, false, true ><<<warpBlocks, TPB>>>(bufBh, L[l].b, bufA, asi, adi, aso, ado, batch, n, O); break;
            case 3: gat_agg_kernel<2, true,  false, true ><<<warpBlocks, TPB>>>(bufBh, L[l].b, bufA, asi, adi, aso, ado, batch, n, O); break;
            case 4: gat_agg_kernel<1, false, true,  false><<<warpBlocks, TPB>>>(bufBh, L[l].b, bufA, asi, adi, aso, ado, batch, n, O); break;
        }
    }

    final_kernel<<<(GG + TPB - 1) / TPB, TPB>>>((const float*)d_in[29],
                                                (const float*)d_in[30], out);
}

// round 6
// speedup vs baseline: 1.1751x; 1.0638x over previous
#include <cuda_runtime.h>
#include <mma.h>
#include <math.h>

using namespace nvcuda;

#define NN   100000
#define EE   500000
#define ETOT (EE + NN)
#define GG   1000

// ---------------- device scratch (static; no runtime allocation) ----------------
__device__ float d_bufA[(size_t)NN * 256];   // node features (agg out / gemm in)
__device__ float d_bufB[(size_t)NN * 256];   // gemm output (gathered by agg)
__device__ float d_as0[NN], d_ad0[NN];       // alpha ping
__device__ float d_as1[NN], d_ad1[NN];       // alpha pong
__device__ float d_was_all[5 * 256];         // W_l^T a_s per layer
__device__ float d_wad_all[5 * 256];         // W_l^T a_d per layer
__device__ int   d_rowptr[NN + 1];
__device__ int   d_cur[NN];
__device__ int   d_col[ETOT];
__device__ float d_gsum[GG * 32];
__device__ float d_gcnt[GG];
__device__ int   d_blocksum[160];
__device__ int   d_total;

// ---------------- prep (ALL layers, parallel): w_as = W^T a_s, w_ad = W^T a_d ----
struct PrepArgs {
    const float* W[5];
    const float* as_[5];
    const float* ad_[5];
    int I[5];
    int O[5];
};
__global__ void prep_all_kernel(PrepArgs p) {
    __shared__ float sha[4], shd[4];
    int l = blockIdx.y;
    int k = blockIdx.x;
    int I = p.I[l];
    if (k >= I) return;
    int O = p.O[l];
    const float* W = p.W[l];
    const float* as_ = p.as_[l];
    const float* ad_ = p.ad_[l];
    float sa = 0.f, sd = 0.f;
    for (int o = threadIdx.x; o < O; o += 128) {
        float w = W[(size_t)o * I + k];
        sa += w * as_[o];
        sd += w * ad_[o];
    }
    int lane = threadIdx.x & 31, wid = threadIdx.x >> 5;
#pragma unroll
    for (int o = 16; o; o >>= 1) {
        sa += __shfl_xor_sync(0xffffffffu, sa, o);
        sd += __shfl_xor_sync(0xffffffffu, sd, o);
    }
    if (lane == 0) { sha[wid] = sa; shd[wid] = sd; }
    __syncthreads();
    if (threadIdx.x == 0) {
        float ta = sha[0] + sha[1] + sha[2] + sha[3];
        float td = shd[0] + shd[1] + shd[2] + shd[3];
        d_was_all[l * 256 + k] = ta;
        d_wad_all[l * 256 + k] = td;
    }
}

// ---------------- MLP: x[N,1]->16->32->64 relu; fused layer-1 alpha --------------
__global__ void mlp_kernel(const float* __restrict__ x,
                           const float* __restrict__ w1, const float* __restrict__ b1,
                           const float* __restrict__ w2, const float* __restrict__ b2,
                           const float* __restrict__ w3, const float* __restrict__ b3,
                           float* __restrict__ out,
                           const float* __restrict__ was, const float* __restrict__ wad,
                           float* __restrict__ as_out, float* __restrict__ ad_out, int n) {
    __shared__ float s_w1[16], s_b1[16];
    __shared__ float s_w2t[16 * 32];
    __shared__ float s_b2[32];
    __shared__ float s_w3t[32 * 64];
    __shared__ float s_b3[64];
    __shared__ float s_was[64], s_wad[64];

    int tid = threadIdx.x;
    if (tid < 16) { s_w1[tid] = w1[tid]; s_b1[tid] = b1[tid]; }
    if (tid < 32) s_b2[tid] = b2[tid];
    if (tid < 64) { s_b3[tid] = b3[tid]; s_was[tid] = was[tid]; s_wad[tid] = wad[tid]; }
    for (int idx = tid; idx < 32 * 16; idx += blockDim.x) {
        int o = idx / 16, k = idx % 16;
        s_w2t[k * 32 + o] = w2[idx];
    }
    for (int idx = tid; idx < 64 * 32; idx += blockDim.x) {
        int o = idx / 32, k = idx % 32;
        s_w3t[k * 64 + o] = w3[idx];
    }
    __syncthreads();

    int warp = (blockIdx.x * blockDim.x + tid) >> 5;
    int lane = tid & 31;
    if (warp >= n) return;

    float xv = x[warp];
    float h1[16];
#pragma unroll
    for (int j = 0; j < 16; j++) {
        float v = s_w1[j] * xv + s_b1[j];
        h1[j] = v > 0.f ? v : 0.f;
    }
    float h2;
    {
        float acc = s_b2[lane];
#pragma unroll
        for (int k = 0; k < 16; k++) acc += s_w2t[k * 32 + lane] * h1[k];
        h2 = acc > 0.f ? acc : 0.f;
    }
    float v0, v1;
#pragma unroll
    for (int j2 = 0; j2 < 2; j2++) {
        int j = lane + 32 * j2;
        float acc = s_b3[j];
#pragma unroll
        for (int k = 0; k < 32; k++)
            acc += __shfl_sync(0xffffffffu, h2, k) * s_w3t[k * 64 + j];
        acc = acc > 0.f ? acc : 0.f;
        out[(size_t)warp * 64 + j] = acc;
        if (j2 == 0) v0 = acc; else v1 = acc;
    }
    float sa = v0 * s_was[lane] + v1 * s_was[lane + 32];
    float sd = v0 * s_wad[lane] + v1 * s_wad[lane + 32];
#pragma unroll
    for (int o = 16; o; o >>= 1) {
        sa += __shfl_xor_sync(0xffffffffu, sa, o);
        sd += __shfl_xor_sync(0xffffffffu, sd, o);
    }
    if (lane == 0) { as_out[warp] = sa; ad_out[warp] = sd; }
}

// ---------------- CSR build ------------------------------------------------------
__global__ void init_deg_kernel(int n) {
    int i = blockIdx.x * blockDim.x + threadIdx.x;
    if (i < n) d_cur[i] = 1;
}
__global__ void count_deg_kernel(const int* __restrict__ dst, int E) {
    int e = blockIdx.x * blockDim.x + threadIdx.x;
    if (e < E) atomicAdd(&d_cur[dst[e]], 1);
}
__global__ void scan_block_kernel(int n) {
    __shared__ int warpsum[32];
    int i = blockIdx.x * 1024 + threadIdx.x;
    int lane = threadIdx.x & 31, wid = threadIdx.x >> 5;
    int v = (i < n) ? d_cur[i] : 0;
    int x = v;
#pragma unroll
    for (int o = 1; o < 32; o <<= 1) {
        int t = __shfl_up_sync(0xffffffffu, x, o);
        if (lane >= o) x += t;
    }
    if (lane == 31) warpsum[wid] = x;
    __syncthreads();
    if (wid == 0) {
        int s = warpsum[lane];
#pragma unroll
        for (int o = 1; o < 32; o <<= 1) {
            int t = __shfl_up_sync(0xffffffffu, s, o);
            if (lane >= o) s += t;
        }
        warpsum[lane] = s;
    }
    __syncthreads();
    int base = wid ? warpsum[wid - 1] : 0;
    int incl = base + x;
    if (i < n) d_rowptr[i] = incl - v;
    if (threadIdx.x == 1023) d_blocksum[blockIdx.x] = incl;
}
__global__ void scan_sums_kernel(int nb) {
    __shared__ int ws[4];
    int lane = threadIdx.x & 31, wid = threadIdx.x >> 5;
    int v = ((int)threadIdx.x < nb) ? d_blocksum[threadIdx.x] : 0;
    int x = v;
#pragma unroll
    for (int o = 1; o < 32; o <<= 1) {
        int t = __shfl_up_sync(0xffffffffu, x, o);
        if (lane >= o) x += t;
    }
    if (lane == 31) ws[wid] = x;
    __syncthreads();
    int add = 0;
    for (int w0 = 0; w0 < wid; w0++) add += ws[w0];
    int incl = add + x;
    d_blocksum[threadIdx.x] = incl - v;
    if ((int)threadIdx.x == nb - 1) d_total = incl;
}
__global__ void scan_add_kernel(int n) {
    int i = blockIdx.x * 1024 + threadIdx.x;
    if (i < n) d_rowptr[i] += d_blocksum[blockIdx.x];
    else if (i == n) d_rowptr[n] = d_total;
}
__global__ void fill_self_kernel(int n) {
    int i = blockIdx.x * blockDim.x + threadIdx.x;
    if (i < n) {
        int r = d_rowptr[i];
        d_col[r] = i;
        d_cur[i] = r + 1;
    }
}
__global__ void scatter_edges_kernel(const int* __restrict__ src,
                                     const int* __restrict__ dst, int E) {
    int e = blockIdx.x * blockDim.x + threadIdx.x;
    if (e < E) {
        int p = atomicAdd(&d_cur[dst[e]], 1);
        d_col[p] = src[e];
    }
}

// ---------------- TF32 GEMM: C[n,O] = A[n,I] @ W[O,I]^T (fp32 out) ---------------
// 128x64 tile, BK=32, 256 threads, direct fragment stores (R3-proven).
#define GLD 36
__global__ void gemm_tf32_kernel(const float* __restrict__ A, const float* __restrict__ W,
                                 float* __restrict__ C, int n, int I, int O) {
    __shared__ float As[128 * GLD];
    __shared__ float Bs[64 * GLD];
    int tid = threadIdx.x;
    int w = tid >> 5;
    int wm = w & 3, wn = w >> 2;
    int bm = blockIdx.y * 128, bn = blockIdx.x * 64;

    wmma::fragment<wmma::accumulator, 16, 16, 8, float> acc[2][2];
#pragma unroll
    for (int i = 0; i < 2; i++)
#pragma unroll
        for (int j = 0; j < 2; j++) wmma::fill_fragment(acc[i][j], 0.f);

    for (int k0 = 0; k0 < I; k0 += 32) {
#pragma unroll
        for (int t = 0; t < 4; t++) {
            int idx = tid * 4 + t;
            int r = idx >> 3, kq = (idx & 7) * 4;
            int ar = bm + r;
            float4 av = make_float4(0.f, 0.f, 0.f, 0.f);
            if (ar < n) av = *(const float4*)(A + (size_t)ar * I + k0 + kq);
            *(float4*)(As + r * GLD + kq) = av;
        }
#pragma unroll
        for (int t = 0; t < 2; t++) {
            int idx = tid * 2 + t;
            int r = idx >> 3, kq = (idx & 7) * 4;
            int br = bn + r;
            float4 bv = make_float4(0.f, 0.f, 0.f, 0.f);
            if (br < O) bv = *(const float4*)(W + (size_t)br * I + k0 + kq);
            *(float4*)(Bs + r * GLD + kq) = bv;
        }
        __syncthreads();
#pragma unroll
        for (int kk = 0; kk < 32; kk += 8) {
            wmma::fragment<wmma::matrix_a, 16, 16, 8, wmma::precision::tf32, wmma::row_major> af[2];
            wmma::fragment<wmma::matrix_b, 16, 16, 8, wmma::precision::tf32, wmma::col_major> bf[2];
            wmma::load_matrix_sync(af[0], As + (wm * 32) * GLD + kk, GLD);
            wmma::load_matrix_sync(af[1], As + (wm * 32 + 16) * GLD + kk, GLD);
            wmma::load_matrix_sync(bf[0], Bs + (wn * 32) * GLD + kk, GLD);
            wmma::load_matrix_sync(bf[1], Bs + (wn * 32 + 16) * GLD + kk, GLD);
#pragma unroll
            for (int i = 0; i < 2; i++)
#pragma unroll
                for (int j = 0; j < 2; j++)
                    wmma::mma_sync(acc[i][j], af[i], bf[j], acc[i][j]);
        }
        __syncthreads();
    }
#pragma unroll
    for (int i = 0; i < 2; i++) {
        int r0 = bm + wm * 32 + i * 16;
        if (r0 >= n) continue;
#pragma unroll
        for (int j = 0; j < 2; j++) {
            int c0 = bn + wn * 32 + j * 16;
            if (c0 < O)
                wmma::store_matrix_sync(C + (size_t)r0 * O + c0, acc[i][j], O,
                                        wmma::mem_row_major);
        }
    }
}

// ---------------- GAT aggregate: warp per dst node, fp32 gather, fused alpha -----
template <int CPL, bool ZPOOL, bool POOL, bool ALPHA>
__global__ void gat_agg_kernel(const float* __restrict__ hlin,
                               const float* __restrict__ bias,
                               float* __restrict__ out,
                               const float* __restrict__ as_in,
                               const float* __restrict__ ad_in,
                               float* __restrict__ as_out,
                               float* __restrict__ ad_out,
                               const float* __restrict__ was_next,
                               const float* __restrict__ wad_next,
                               const int* __restrict__ batch, int n, int O) {
    __shared__ float s_was[256], s_wad[256];
    int tid = threadIdx.x;
    if (ALPHA && tid < O) { s_was[tid] = was_next[tid]; s_wad[tid] = wad_next[tid]; }
    if (ALPHA) __syncthreads();

    int gt = blockIdx.x * blockDim.x + tid;
    if (ZPOOL) {
        if (gt < GG * 32) d_gsum[gt] = 0.f;
        if (gt < GG) d_gcnt[gt] = 0.f;
    }
    int warp = gt >> 5;
    int lane = tid & 31;
    if (warp >= n) return;
    int s = d_rowptr[warp];
    int e = d_rowptr[warp + 1];
    float adi = ad_in[warp];

    float m = -1e30f;
    for (int p = s + lane; p < e; p += 32) {
        float v = as_in[d_col[p]] + adi;
        v = v > 0.f ? v : 0.2f * v;
        m = fmaxf(m, v);
    }
#pragma unroll
    for (int o = 16; o; o >>= 1) m = fmaxf(m, __shfl_xor_sync(0xffffffffu, m, o));

    float den = 0.f;
    float acc[CPL];
#pragma unroll
    for (int c = 0; c < CPL; c++) acc[c] = 0.f;

    for (int p0 = s; p0 < e; p0 += 32) {
        int p = p0 + lane;
        float wgt = 0.f;
        int src = 0;
        if (p < e) {
            src = d_col[p];
            float v = as_in[src] + adi;
            v = v > 0.f ? v : 0.2f * v;
            wgt = __expf(v - m);
            den += wgt;
        }
        int cnt = min(32, e - p0);
        for (int q = 0; q < cnt; q++) {
            float wq = __shfl_sync(0xffffffffu, wgt, q);
            int   sq = __shfl_sync(0xffffffffu, src, q);
            const float* row = hlin + (size_t)sq * O;
            if (CPL == 1) {
                acc[0] += wq * row[lane];
            } else if (CPL == 2) {
                float2 v2 = ((const float2*)row)[lane];
                acc[0] += wq * v2.x; acc[1] += wq * v2.y;
            } else if (CPL == 4) {
                float4 v4 = ((const float4*)row)[lane];
                acc[0] += wq * v4.x; acc[1] += wq * v4.y;
                acc[2] += wq * v4.z; acc[3] += wq * v4.w;
            } else {   // CPL == 8
                float4 v4 = ((const float4*)row)[2 * lane];
                float4 u4 = ((const float4*)row)[2 * lane + 1];
                acc[0] += wq * v4.x; acc[1] += wq * v4.y;
                acc[2] += wq * v4.z; acc[3] += wq * v4.w;
                acc[4] += wq * u4.x; acc[5] += wq * u4.y;
                acc[6] += wq * u4.z; acc[7] += wq * u4.w;
            }
        }
    }
#pragma unroll
    for (int o = 16; o; o >>= 1) den += __shfl_xor_sync(0xffffffffu, den, o);
    float inv = 1.f / den;

    // channels are contiguous per lane: ch = CPL*lane + c
    float v[CPL];
#pragma unroll
    for (int c = 0; c < CPL; c++) {
        float t = acc[c] * inv + bias[CPL * lane + c];
        v[c] = t > 0.f ? t : 0.f;
    }

    float* orow = out + (size_t)warp * O;
    if (CPL == 1) {
        orow[lane] = v[0];
        if (POOL) {
            int b = batch[warp];
            atomicAdd(&d_gsum[b * 32 + lane], v[0]);
            if (lane == 0) atomicAdd(&d_gcnt[b], 1.f);
        }
    } else if (CPL == 2) {
        ((float2*)orow)[lane] = make_float2(v[0], v[1]);
    } else if (CPL == 4) {
        ((float4*)orow)[lane] = make_float4(v[0], v[1], v[2], v[3]);
    } else {
        ((float4*)orow)[2 * lane]     = make_float4(v[0], v[1], v[2], v[3]);
        ((float4*)orow)[2 * lane + 1] = make_float4(v[4], v[5], v[6], v[7]);
    }

    if (ALPHA) {
        float sa = 0.f, sd = 0.f;
#pragma unroll
        for (int c = 0; c < CPL; c++) {
            int ch = CPL * lane + c;
            sa += v[c] * s_was[ch];
            sd += v[c] * s_wad[ch];
        }
#pragma unroll
        for (int o = 16; o; o >>= 1) {
            sa += __shfl_xor_sync(0xffffffffu, sa, o);
            sd += __shfl_xor_sync(0xffffffffu, sd, o);
        }
        if (lane == 0) { as_out[warp] = sa; ad_out[warp] = sd; }
    }
}

// ---------------- final linear + sigmoid ------------------------------------------
__global__ void final_kernel(const float* __restrict__ lw, const float* __restrict__ lb,
                             float* __restrict__ out) {
    int g = blockIdx.x * blockDim.x + threadIdx.x;
    if (g >= GG) return;
    float cnt = fmaxf(d_gcnt[g], 1.f);
    float acc = lb[0];
#pragma unroll
    for (int c = 0; c < 32; c++) acc += (d_gsum[g * 32 + c] / cnt) * lw[c];
    out[g] = 1.f / (1.f + __expf(-acc));
}

// ---------------- launch ----------------------------------------------------------
extern "C" void kernel_launch(void* const* d_in, const int* in_sizes, int n_in,
                              void* d_out, int out_size) {
    const float* x     = (const float*)d_in[0];
    const int*   ei    = (const int*)d_in[1];
    const int*   batch = (const int*)d_in[2];
    const float* w1 = (const float*)d_in[3]; const float* b1 = (const float*)d_in[4];
    const float* w2 = (const float*)d_in[5]; const float* b2 = (const float*)d_in[6];
    const float* w3 = (const float*)d_in[7]; const float* b3 = (const float*)d_in[8];
    float* out = (float*)d_out;

    int n = in_sizes[0];
    int E = in_sizes[1] / 2;
    const int* src = ei;
    const int* dst = ei + E;

    float *bufA, *bufB, *as0, *ad0, *as1, *ad1, *wasAll, *wadAll;
    cudaGetSymbolAddress((void**)&bufA, d_bufA);
    cudaGetSymbolAddress((void**)&bufB, d_bufB);
    cudaGetSymbolAddress((void**)&as0, d_as0);
    cudaGetSymbolAddress((void**)&ad0, d_ad0);
    cudaGetSymbolAddress((void**)&as1, d_as1);
    cudaGetSymbolAddress((void**)&ad1, d_ad1);
    cudaGetSymbolAddress((void**)&wasAll, d_was_all);
    cudaGetSymbolAddress((void**)&wadAll, d_wad_all);

    const int TPB = 256;
    int warpBlocks = (n * 32 + TPB - 1) / TPB;

    struct Layer { const float *W, *as_, *ad_, *b; int I, O; };
    Layer L[5] = {
        { (const float*)d_in[9],  (const float*)d_in[10], (const float*)d_in[11], (const float*)d_in[12],  64, 128 },
        { (const float*)d_in[13], (const float*)d_in[14], (const float*)d_in[15], (const float*)d_in[16], 128, 256 },
        { (const float*)d_in[17], (const float*)d_in[18], (const float*)d_in[19], (const float*)d_in[20], 256, 128 },
        { (const float*)d_in[21], (const float*)d_in[22], (const float*)d_in[23], (const float*)d_in[24], 128,  64 },
        { (const float*)d_in[25], (const float*)d_in[26], (const float*)d_in[27], (const float*)d_in[28],  64,  32 },
    };

    // prep all layers' alpha-weight vectors in one parallel kernel
    PrepArgs pa;
    for (int l = 0; l < 5; l++) {
        pa.W[l] = L[l].W; pa.as_[l] = L[l].as_; pa.ad_[l] = L[l].ad_;
        pa.I[l] = L[l].I; pa.O[l] = L[l].O;
    }
    prep_all_kernel<<<dim3(256, 5), 128>>>(pa);

    // MLP with fused layer-1 alpha (-> set 0)
    mlp_kernel<<<warpBlocks, TPB>>>(x, w1, b1, w2, b2, w3, b3, bufA,
                                    wasAll, wadAll, as0, ad0, n);

    // CSR build
    init_deg_kernel<<<(n + TPB - 1) / TPB, TPB>>>(n);
    count_deg_kernel<<<(E + TPB - 1) / TPB, TPB>>>(dst, E);
    int nb = (n + 1023) / 1024;
    scan_block_kernel<<<nb, 1024>>>(n);
    scan_sums_kernel<<<1, 128>>>(nb);
    scan_add_kernel<<<(n + 1024) / 1024, 1024>>>(n);
    fill_self_kernel<<<(n + TPB - 1) / TPB, TPB>>>(n);
    scatter_edges_kernel<<<(E + TPB - 1) / TPB, TPB>>>(src, dst, E);

    for (int l = 0; l < 5; l++) {
        int I = L[l].I, O = L[l].O;
        dim3 grid((O + 63) / 64, (n + 127) / 128);
        gemm_tf32_kernel<<<grid, 256>>>(bufA, L[l].W, bufB, n, I, O);
        const float* asi = (l & 1) ? as1 : as0;
        const float* adi = (l & 1) ? ad1 : ad0;
        float* aso = (l & 1) ? as0 : as1;
        float* ado = (l & 1) ? ad0 : ad1;
        const float* wn_ = wasAll + (l + 1) * 256;
        const float* wd_ = wadAll + (l + 1) * 256;
        switch (l) {
            case 0: gat_agg_kernel<4, false, false, true ><<<warpBlocks, TPB>>>(bufB, L[l].b, bufA, asi, adi, aso, ado, wn_, wd_, batch, n, O); break;
            case 1: gat_agg_kernel<8, false, false, true ><<<warpBlocks, TPB>>>(bufB, L[l].b, bufA, asi, adi, aso, ado, wn_, wd_, batch, n, O); break;
            case 2: gat_agg_kernel<4, false, false, true ><<<warpBlocks, TPB>>>(bufB, L[l].b, bufA, asi, adi, aso, ado, wn_, wd_, batch, n, O); break;
            case 3: gat_agg_kernel<2, true,  false, true ><<<warpBlocks, TPB>>>(bufB, L[l].b, bufA, asi, adi, aso, ado, wn_, wd_, batch, n, O); break;
            case 4: gat_agg_kernel<1, false, true,  false><<<warpBlocks, TPB>>>(bufB, L[l].b, bufA, asi, adi, aso, ado, wn_, wd_, batch, n, O); break;
        }
    }

    final_kernel<<<(GG + TPB - 1) / TPB, TPB>>>((const float*)d_in[29],
                                                (const float*)d_in[30], out);
}

// round 7
// speedup vs baseline: 1.1891x; 1.0119x over previous
#include <cuda_runtime.h>
#include <mma.h>
#include <math.h>

using namespace nvcuda;

#define NN   100000
#define EE   500000
#define ETOT (EE + NN)
#define GG   1000

// ---------------- device scratch (static; no runtime allocation) ----------------
__device__ float d_bufA[(size_t)NN * 256];   // node features (agg out / gemm in)
__device__ float d_bufB[(size_t)NN * 256];   // gemm output (gathered by agg)
__device__ float d_as0[NN], d_ad0[NN];       // alpha ping
__device__ float d_as1[NN], d_ad1[NN];       // alpha pong
__device__ float d_was_all[5 * 256];         // W_l^T a_s per layer
__device__ float d_wad_all[5 * 256];         // W_l^T a_d per layer
__device__ int   d_rowptr[NN + 1];
__device__ int   d_cur[NN];
__device__ int   d_col[ETOT];
__device__ float d_gsum[GG * 32];
__device__ float d_gcnt[GG];
__device__ int   d_blocksum[160];
__device__ int   d_total;

// ---------------- prep (ALL layers, parallel): w_as = W^T a_s, w_ad = W^T a_d ----
struct PrepArgs {
    const float* W[5];
    const float* as_[5];
    const float* ad_[5];
    int I[5];
    int O[5];
};
__global__ void prep_all_kernel(PrepArgs p) {
    __shared__ float sha[4], shd[4];
    int l = blockIdx.y;
    int k = blockIdx.x;
    int I = p.I[l];
    if (k >= I) return;
    int O = p.O[l];
    const float* W = p.W[l];
    const float* as_ = p.as_[l];
    const float* ad_ = p.ad_[l];
    float sa = 0.f, sd = 0.f;
    for (int o = threadIdx.x; o < O; o += 128) {
        float w = W[(size_t)o * I + k];
        sa += w * as_[o];
        sd += w * ad_[o];
    }
    int lane = threadIdx.x & 31, wid = threadIdx.x >> 5;
#pragma unroll
    for (int o = 16; o; o >>= 1) {
        sa += __shfl_xor_sync(0xffffffffu, sa, o);
        sd += __shfl_xor_sync(0xffffffffu, sd, o);
    }
    if (lane == 0) { sha[wid] = sa; shd[wid] = sd; }
    __syncthreads();
    if (threadIdx.x == 0) {
        d_was_all[l * 256 + k] = sha[0] + sha[1] + sha[2] + sha[3];
        d_wad_all[l * 256 + k] = shd[0] + shd[1] + shd[2] + shd[3];
    }
}

// ---------------- MLP: x[N,1]->16->32->64 relu; fused layer-1 alpha --------------
__global__ void mlp_kernel(const float* __restrict__ x,
                           const float* __restrict__ w1, const float* __restrict__ b1,
                           const float* __restrict__ w2, const float* __restrict__ b2,
                           const float* __restrict__ w3, const float* __restrict__ b3,
                           float* __restrict__ out,
                           const float* __restrict__ was, const float* __restrict__ wad,
                           float* __restrict__ as_out, float* __restrict__ ad_out, int n) {
    __shared__ float s_w1[16], s_b1[16];
    __shared__ float s_w2t[16 * 32];
    __shared__ float s_b2[32];
    __shared__ float s_w3t[32 * 64];
    __shared__ float s_b3[64];
    __shared__ float s_was[64], s_wad[64];

    int tid = threadIdx.x;
    if (tid < 16) { s_w1[tid] = w1[tid]; s_b1[tid] = b1[tid]; }
    if (tid < 32) s_b2[tid] = b2[tid];
    if (tid < 64) { s_b3[tid] = b3[tid]; s_was[tid] = was[tid]; s_wad[tid] = wad[tid]; }
    for (int idx = tid; idx < 32 * 16; idx += blockDim.x) {
        int o = idx / 16, k = idx % 16;
        s_w2t[k * 32 + o] = w2[idx];
    }
    for (int idx = tid; idx < 64 * 32; idx += blockDim.x) {
        int o = idx / 32, k = idx % 32;
        s_w3t[k * 64 + o] = w3[idx];
    }
    __syncthreads();

    int warp = (blockIdx.x * blockDim.x + tid) >> 5;
    int lane = tid & 31;
    if (warp >= n) return;

    float xv = x[warp];
    float h1[16];
#pragma unroll
    for (int j = 0; j < 16; j++) {
        float v = s_w1[j] * xv + s_b1[j];
        h1[j] = v > 0.f ? v : 0.f;
    }
    float h2;
    {
        float acc = s_b2[lane];
#pragma unroll
        for (int k = 0; k < 16; k++) acc += s_w2t[k * 32 + lane] * h1[k];
        h2 = acc > 0.f ? acc : 0.f;
    }
    float v0, v1;
#pragma unroll
    for (int j2 = 0; j2 < 2; j2++) {
        int j = lane + 32 * j2;
        float acc = s_b3[j];
#pragma unroll
        for (int k = 0; k < 32; k++)
            acc += __shfl_sync(0xffffffffu, h2, k) * s_w3t[k * 64 + j];
        acc = acc > 0.f ? acc : 0.f;
        out[(size_t)warp * 64 + j] = acc;
        if (j2 == 0) v0 = acc; else v1 = acc;
    }
    float sa = v0 * s_was[lane] + v1 * s_was[lane + 32];
    float sd = v0 * s_wad[lane] + v1 * s_wad[lane + 32];
#pragma unroll
    for (int o = 16; o; o >>= 1) {
        sa += __shfl_xor_sync(0xffffffffu, sa, o);
        sd += __shfl_xor_sync(0xffffffffu, sd, o);
    }
    if (lane == 0) { as_out[warp] = sa; ad_out[warp] = sd; }
}

// ---------------- CSR build ------------------------------------------------------
__global__ void init_deg_kernel(int n) {
    int i = blockIdx.x * blockDim.x + threadIdx.x;
    if (i < n) d_cur[i] = 1;
}
__global__ void count_deg_kernel(const int* __restrict__ dst, int E) {
    int e = blockIdx.x * blockDim.x + threadIdx.x;
    if (e < E) atomicAdd(&d_cur[dst[e]], 1);
}
__global__ void scan_block_kernel(int n) {
    __shared__ int warpsum[32];
    int i = blockIdx.x * 1024 + threadIdx.x;
    int lane = threadIdx.x & 31, wid = threadIdx.x >> 5;
    int v = (i < n) ? d_cur[i] : 0;
    int x = v;
#pragma unroll
    for (int o = 1; o < 32; o <<= 1) {
        int t = __shfl_up_sync(0xffffffffu, x, o);
        if (lane >= o) x += t;
    }
    if (lane == 31) warpsum[wid] = x;
    __syncthreads();
    if (wid == 0) {
        int s = warpsum[lane];
#pragma unroll
        for (int o = 1; o < 32; o <<= 1) {
            int t = __shfl_up_sync(0xffffffffu, s, o);
            if (lane >= o) s += t;
        }
        warpsum[lane] = s;
    }
    __syncthreads();
    int base = wid ? warpsum[wid - 1] : 0;
    int incl = base + x;
    if (i < n) d_rowptr[i] = incl - v;
    if (threadIdx.x == 1023) d_blocksum[blockIdx.x] = incl;
}
__global__ void scan_sums_kernel(int nb) {
    __shared__ int ws[4];
    int lane = threadIdx.x & 31, wid = threadIdx.x >> 5;
    int v = ((int)threadIdx.x < nb) ? d_blocksum[threadIdx.x] : 0;
    int x = v;
#pragma unroll
    for (int o = 1; o < 32; o <<= 1) {
        int t = __shfl_up_sync(0xffffffffu, x, o);
        if (lane >= o) x += t;
    }
    if (lane == 31) ws[wid] = x;
    __syncthreads();
    int add = 0;
    for (int w0 = 0; w0 < wid; w0++) add += ws[w0];
    int incl = add + x;
    d_blocksum[threadIdx.x] = incl - v;
    if ((int)threadIdx.x == nb - 1) d_total = incl;
}
__global__ void scan_add_kernel(int n) {
    int i = blockIdx.x * 1024 + threadIdx.x;
    if (i < n) d_rowptr[i] += d_blocksum[blockIdx.x];
    else if (i == n) d_rowptr[n] = d_total;
}
__global__ void fill_self_kernel(int n) {
    int i = blockIdx.x * blockDim.x + threadIdx.x;
    if (i < n) {
        int r = d_rowptr[i];
        d_col[r] = i;
        d_cur[i] = r + 1;
    }
}
__global__ void scatter_edges_kernel(const int* __restrict__ src,
                                     const int* __restrict__ dst, int E) {
    int e = blockIdx.x * blockDim.x + threadIdx.x;
    if (e < E) {
        int p = atomicAdd(&d_cur[dst[e]], 1);
        d_col[p] = src[e];
    }
}

// ---------------- TF32 GEMM: C[n,O] = A[n,I] @ W[O,I]^T (fp32 out) ---------------
// 128xBN tile, BK=32, 256 threads = 8 warps (4m x 2n), warp tile 32 x BN/2.
#define GLD 36
template <int BN>   // 64 or 128
__global__ void gemm_tf32_kernel(const float* __restrict__ A, const float* __restrict__ W,
                                 float* __restrict__ C, int n, int I, int O) {
    constexpr int WN = BN / 2;        // warp n-width
    constexpr int NF = WN / 16;       // B fragments per warp
    constexpr int NLB = BN / 64;      // B float4 loads per thread (2 or 4)
    __shared__ float As[128 * GLD];
    __shared__ float Bs[BN * GLD];
    int tid = threadIdx.x;
    int w = tid >> 5;
    int wm = w & 3, wn = w >> 2;
    int bm = blockIdx.y * 128, bn = blockIdx.x * BN;

    wmma::fragment<wmma::accumulator, 16, 16, 8, float> acc[2][NF];
#pragma unroll
    for (int i = 0; i < 2; i++)
#pragma unroll
        for (int j = 0; j < NF; j++) wmma::fill_fragment(acc[i][j], 0.f);

    for (int k0 = 0; k0 < I; k0 += 32) {
#pragma unroll
        for (int t = 0; t < 4; t++) {
            int idx = tid * 4 + t;
            int r = idx >> 3, kq = (idx & 7) * 4;
            int ar = bm + r;
            float4 av = make_float4(0.f, 0.f, 0.f, 0.f);
            if (ar < n) av = *(const float4*)(A + (size_t)ar * I + k0 + kq);
            *(float4*)(As + r * GLD + kq) = av;
        }
#pragma unroll
        for (int t = 0; t < NLB; t++) {
            int idx = tid * NLB + t;
            int r = idx >> 3, kq = (idx & 7) * 4;
            int br = bn + r;
            float4 bv = make_float4(0.f, 0.f, 0.f, 0.f);
            if (br < O) bv = *(const float4*)(W + (size_t)br * I + k0 + kq);
            *(float4*)(Bs + r * GLD + kq) = bv;
        }
        __syncthreads();
#pragma unroll
        for (int kk = 0; kk < 32; kk += 8) {
            wmma::fragment<wmma::matrix_a, 16, 16, 8, wmma::precision::tf32, wmma::row_major> af[2];
            wmma::fragment<wmma::matrix_b, 16, 16, 8, wmma::precision::tf32, wmma::col_major> bf[NF];
            wmma::load_matrix_sync(af[0], As + (wm * 32) * GLD + kk, GLD);
            wmma::load_matrix_sync(af[1], As + (wm * 32 + 16) * GLD + kk, GLD);
#pragma unroll
            for (int j = 0; j < NF; j++)
                wmma::load_matrix_sync(bf[j], Bs + (wn * WN + j * 16) * GLD + kk, GLD);
#pragma unroll
            for (int i = 0; i < 2; i++)
#pragma unroll
                for (int j = 0; j < NF; j++)
                    wmma::mma_sync(acc[i][j], af[i], bf[j], acc[i][j]);
        }
        __syncthreads();
    }
#pragma unroll
    for (int i = 0; i < 2; i++) {
        int r0 = bm + wm * 32 + i * 16;
        if (r0 >= n) continue;
#pragma unroll
        for (int j = 0; j < NF; j++) {
            int c0 = bn + wn * WN + j * 16;
            if (c0 < O)
                wmma::store_matrix_sync(C + (size_t)r0 * O + c0, acc[i][j], O,
                                        wmma::mem_row_major);
        }
    }
}

// ---------------- GAT aggregate: warp per dst node, 2x-unrolled gather -----------
template <int CPL, bool ZPOOL, bool POOL, bool ALPHA>
__global__ void gat_agg_kernel(const float* __restrict__ hlin,
                               const float* __restrict__ bias,
                               float* __restrict__ out,
                               const float* __restrict__ as_in,
                               const float* __restrict__ ad_in,
                               float* __restrict__ as_out,
                               float* __restrict__ ad_out,
                               const float* __restrict__ was_next,
                               const float* __restrict__ wad_next,
                               const int* __restrict__ batch, int n, int O) {
    __shared__ float s_was[256], s_wad[256];
    int tid = threadIdx.x;
    if (ALPHA && tid < O) { s_was[tid] = was_next[tid]; s_wad[tid] = wad_next[tid]; }
    if (ALPHA) __syncthreads();

    int gt = blockIdx.x * blockDim.x + tid;
    if (ZPOOL) {
        if (gt < GG * 32) d_gsum[gt] = 0.f;
        if (gt < GG) d_gcnt[gt] = 0.f;
    }
    int warp = gt >> 5;
    int lane = tid & 31;
    if (warp >= n) return;
    int s = d_rowptr[warp];
    int e = d_rowptr[warp + 1];
    float adi = ad_in[warp];

    float m = -1e30f;
    for (int p = s + lane; p < e; p += 32) {
        float v = as_in[d_col[p]] + adi;
        v = v > 0.f ? v : 0.2f * v;
        m = fmaxf(m, v);
    }
#pragma unroll
    for (int o = 16; o; o >>= 1) m = fmaxf(m, __shfl_xor_sync(0xffffffffu, m, o));

    float den = 0.f;
    float acc[CPL];
#pragma unroll
    for (int c = 0; c < CPL; c++) acc[c] = 0.f;

    for (int p0 = s; p0 < e; p0 += 32) {
        int p = p0 + lane;
        float wgt = 0.f;
        int src = 0;
        if (p < e) {
            src = d_col[p];
            float v = as_in[src] + adi;
            v = v > 0.f ? v : 0.2f * v;
            wgt = __expf(v - m);
            den += wgt;
        }
        int cnt = min(32, e - p0);
        int q = 0;
        // 2x-unrolled gather: two independent row loads in flight
        for (; q + 1 < cnt; q += 2) {
            float wq0 = __shfl_sync(0xffffffffu, wgt, q);
            int   sq0 = __shfl_sync(0xffffffffu, src, q);
            float wq1 = __shfl_sync(0xffffffffu, wgt, q + 1);
            int   sq1 = __shfl_sync(0xffffffffu, src, q + 1);
            const float* r0 = hlin + (size_t)sq0 * O;
            const float* r1 = hlin + (size_t)sq1 * O;
            if (CPL == 1) {
                float a0 = r0[lane];
                float a1 = r1[lane];
                acc[0] += wq0 * a0 + wq1 * a1;
            } else if (CPL == 2) {
                float2 a0 = ((const float2*)r0)[lane];
                float2 a1 = ((const float2*)r1)[lane];
                acc[0] += wq0 * a0.x + wq1 * a1.x;
                acc[1] += wq0 * a0.y + wq1 * a1.y;
            } else if (CPL == 4) {
                float4 a0 = ((const float4*)r0)[lane];
                float4 a1 = ((const float4*)r1)[lane];
                acc[0] += wq0 * a0.x + wq1 * a1.x;
                acc[1] += wq0 * a0.y + wq1 * a1.y;
                acc[2] += wq0 * a0.z + wq1 * a1.z;
                acc[3] += wq0 * a0.w + wq1 * a1.w;
            } else {
                float4 a0 = ((const float4*)r0)[2 * lane];
                float4 b0 = ((const float4*)r0)[2 * lane + 1];
                float4 a1 = ((const float4*)r1)[2 * lane];
                float4 b1 = ((const float4*)r1)[2 * lane + 1];
                acc[0] += wq0 * a0.x + wq1 * a1.x;
                acc[1] += wq0 * a0.y + wq1 * a1.y;
                acc[2] += wq0 * a0.z + wq1 * a1.z;
                acc[3] += wq0 * a0.w + wq1 * a1.w;
                acc[4] += wq0 * b0.x + wq1 * b1.x;
                acc[5] += wq0 * b0.y + wq1 * b1.y;
                acc[6] += wq0 * b0.z + wq1 * b1.z;
                acc[7] += wq0 * b0.w + wq1 * b1.w;
            }
        }
        if (q < cnt) {
            float wq = __shfl_sync(0xffffffffu, wgt, q);
            int   sq = __shfl_sync(0xffffffffu, src, q);
            const float* row = hlin + (size_t)sq * O;
            if (CPL == 1) {
                acc[0] += wq * row[lane];
            } else if (CPL == 2) {
                float2 v2 = ((const float2*)row)[lane];
                acc[0] += wq * v2.x; acc[1] += wq * v2.y;
            } else if (CPL == 4) {
                float4 v4 = ((const float4*)row)[lane];
                acc[0] += wq * v4.x; acc[1] += wq * v4.y;
                acc[2] += wq * v4.z; acc[3] += wq * v4.w;
            } else {
                float4 v4 = ((const float4*)row)[2 * lane];
                float4 u4 = ((const float4*)row)[2 * lane + 1];
                acc[0] += wq * v4.x; acc[1] += wq * v4.y;
                acc[2] += wq * v4.z; acc[3] += wq * v4.w;
                acc[4] += wq * u4.x; acc[5] += wq * u4.y;
                acc[6] += wq * u4.z; acc[7] += wq * u4.w;
            }
        }
    }
#pragma unroll
    for (int o = 16; o; o >>= 1) den += __shfl_xor_sync(0xffffffffu, den, o);
    float inv = 1.f / den;

    float v[CPL];
#pragma unroll
    for (int c = 0; c < CPL; c++) {
        float t = acc[c] * inv + bias[CPL * lane + c];
        v[c] = t > 0.f ? t : 0.f;
    }

    float* orow = out + (size_t)warp * O;
    if (CPL == 1) {
        orow[lane] = v[0];
        if (POOL) {
            int b = batch[warp];
            atomicAdd(&d_gsum[b * 32 + lane], v[0]);
            if (lane == 0) atomicAdd(&d_gcnt[b], 1.f);
        }
    } else if (CPL == 2) {
        ((float2*)orow)[lane] = make_float2(v[0], v[1]);
    } else if (CPL == 4) {
        ((float4*)orow)[lane] = make_float4(v[0], v[1], v[2], v[3]);
    } else {
        ((float4*)orow)[2 * lane]     = make_float4(v[0], v[1], v[2], v[3]);
        ((float4*)orow)[2 * lane + 1] = make_float4(v[4], v[5], v[6], v[7]);
    }

    if (ALPHA) {
        float sa = 0.f, sd = 0.f;
#pragma unroll
        for (int c = 0; c < CPL; c++) {
            int ch = CPL * lane + c;
            sa += v[c] * s_was[ch];
            sd += v[c] * s_wad[ch];
        }
#pragma unroll
        for (int o = 16; o; o >>= 1) {
            sa += __shfl_xor_sync(0xffffffffu, sa, o);
            sd += __shfl_xor_sync(0xffffffffu, sd, o);
        }
        if (lane == 0) { as_out[warp] = sa; ad_out[warp] = sd; }
    }
}

// ---------------- final linear + sigmoid ------------------------------------------
__global__ void final_kernel(const float* __restrict__ lw, const float* __restrict__ lb,
                             float* __restrict__ out) {
    int g = blockIdx.x * blockDim.x + threadIdx.x;
    if (g >= GG) return;
    float cnt = fmaxf(d_gcnt[g], 1.f);
    float acc = lb[0];
#pragma unroll
    for (int c = 0; c < 32; c++) acc += (d_gsum[g * 32 + c] / cnt) * lw[c];
    out[g] = 1.f / (1.f + __expf(-acc));
}

// ---------------- launch ----------------------------------------------------------
extern "C" void kernel_launch(void* const* d_in, const int* in_sizes, int n_in,
                              void* d_out, int out_size) {
    const float* x     = (const float*)d_in[0];
    const int*   ei    = (const int*)d_in[1];
    const int*   batch = (const int*)d_in[2];
    const float* w1 = (const float*)d_in[3]; const float* b1 = (const float*)d_in[4];
    const float* w2 = (const float*)d_in[5]; const float* b2 = (const float*)d_in[6];
    const float* w3 = (const float*)d_in[7]; const float* b3 = (const float*)d_in[8];
    float* out = (float*)d_out;

    int n = in_sizes[0];
    int E = in_sizes[1] / 2;
    const int* src = ei;
    const int* dst = ei + E;

    float *bufA, *bufB, *as0, *ad0, *as1, *ad1, *wasAll, *wadAll;
    cudaGetSymbolAddress((void**)&bufA, d_bufA);
    cudaGetSymbolAddress((void**)&bufB, d_bufB);
    cudaGetSymbolAddress((void**)&as0, d_as0);
    cudaGetSymbolAddress((void**)&ad0, d_ad0);
    cudaGetSymbolAddress((void**)&as1, d_as1);
    cudaGetSymbolAddress((void**)&ad1, d_ad1);
    cudaGetSymbolAddress((void**)&wasAll, d_was_all);
    cudaGetSymbolAddress((void**)&wadAll, d_wad_all);

    const int TPB = 256;
    int warpBlocks = (n * 32 + TPB - 1) / TPB;

    struct Layer { const float *W, *as_, *ad_, *b; int I, O; };
    Layer L[5] = {
        { (const float*)d_in[9],  (const float*)d_in[10], (const float*)d_in[11], (const float*)d_in[12],  64, 128 },
        { (const float*)d_in[13], (const float*)d_in[14], (const float*)d_in[15], (const float*)d_in[16], 128, 256 },
        { (const float*)d_in[17], (const float*)d_in[18], (const float*)d_in[19], (const float*)d_in[20], 256, 128 },
        { (const float*)d_in[21], (const float*)d_in[22], (const float*)d_in[23], (const float*)d_in[24], 128,  64 },
        { (const float*)d_in[25], (const float*)d_in[26], (const float*)d_in[27], (const float*)d_in[28],  64,  32 },
    };

    PrepArgs pa;
    for (int l = 0; l < 5; l++) {
        pa.W[l] = L[l].W; pa.as_[l] = L[l].as_; pa.ad_[l] = L[l].ad_;
        pa.I[l] = L[l].I; pa.O[l] = L[l].O;
    }
    prep_all_kernel<<<dim3(256, 5), 128>>>(pa);

    mlp_kernel<<<warpBlocks, TPB>>>(x, w1, b1, w2, b2, w3, b3, bufA,
                                    wasAll, wadAll, as0, ad0, n);

    init_deg_kernel<<<(n + TPB - 1) / TPB, TPB>>>(n);
    count_deg_kernel<<<(E + TPB - 1) / TPB, TPB>>>(dst, E);
    int nb = (n + 1023) / 1024;
    scan_block_kernel<<<nb, 1024>>>(n);
    scan_sums_kernel<<<1, 128>>>(nb);
    scan_add_kernel<<<(n + 1024) / 1024, 1024>>>(n);
    fill_self_kernel<<<(n + TPB - 1) / TPB, TPB>>>(n);
    scatter_edges_kernel<<<(E + TPB - 1) / TPB, TPB>>>(src, dst, E);

    for (int l = 0; l < 5; l++) {
        int I = L[l].I, O = L[l].O;
        if (O >= 128) {
            dim3 grid((O + 127) / 128, (n + 127) / 128);
            gemm_tf32_kernel<128><<<grid, 256>>>(bufA, L[l].W, bufB, n, I, O);
        } else {
            dim3 grid((O + 63) / 64, (n + 127) / 128);
            gemm_tf32_kernel<64><<<grid, 256>>>(bufA, L[l].W, bufB, n, I, O);
        }
        const float* asi = (l & 1) ? as1 : as0;
        const float* adi = (l & 1) ? ad1 : ad0;
        float* aso = (l & 1) ? as0 : as1;
        float* ado = (l & 1) ? ad0 : ad1;
        const float* wn_ = wasAll + (l + 1) * 256;
        const float* wd_ = wadAll + (l + 1) * 256;
        switch (l) {
            case 0: gat_agg_kernel<4, false, false, true ><<<warpBlocks, TPB>>>(bufB, L[l].b, bufA, asi, adi, aso, ado, wn_, wd_, batch, n, O); break;
            case 1: gat_agg_kernel<8, false, false, true ><<<warpBlocks, TPB>>>(bufB, L[l].b, bufA, asi, adi, aso, ado, wn_, wd_, batch, n, O); break;
            case 2: gat_agg_kernel<4, false, false, true ><<<warpBlocks, TPB>>>(bufB, L[l].b, bufA, asi, adi, aso, ado, wn_, wd_, batch, n, O); break;
            case 3: gat_agg_kernel<2, true,  false, true ><<<warpBlocks, TPB>>>(bufB, L[l].b, bufA, asi, adi, aso, ado, wn_, wd_, batch, n, O); break;
            case 4: gat_agg_kernel<1, false, true,  false><<<warpBlocks, TPB>>>(bufB, L[l].b, bufA, asi, adi, aso, ado, wn_, wd_, batch, n, O); break;
        }
    }

    final_kernel<<<(GG + TPB - 1) / TPB, TPB>>>((const float*)d_in[29],
                                                (const float*)d_in[30], out);
}